// round 4
// baseline (speedup 1.0000x reference)
#include <cuda_runtime.h>

// InteractionArch: out[b] = concat(dense[b] (128),
//        triu(k=1) of Gram([dense[b]; sparse[b].reshape(26,128)]) (351))
// B=16384, D=128, F=26, OUTW=479.
//
// One warp per sample; lane owns dims lane*4..lane*4+3 (float4).
// Register plan (anti-spill, cap 168 via __launch_bounds__(128,3) -> 12 warps/SM):
//   - hold 19 vectors resident (dense + sparse rows 0..17)         76 regs
//   - stream 8 high vectors (rows 18..25) with depth-2 prefetch     8 regs
//   - reload the 8 (L2-hot) for within-high pairs                  32 regs (after stream regs die)
//   - p[32] chunk buffer                                           32 regs
// Pair partials batched in chunks of 32, reduced by a 31-shuffle halving
// butterfly (lane j ends with chunk pair j), scattered via smem slot->triu
// index table (output rows are L2-resident; scattered STG.32 is fine).

#define FF    26
#define OUTW  479
#define NPAIR 351
#define NLO   19      // resident vectors: dense + sparse rows 0..17
#define BNUM  16384

__device__ __forceinline__ float dot4(const float4 a, const float4 b)
{
    float s = a.x * b.x;
    s = fmaf(a.y, b.y, s);
    s = fmaf(a.z, b.z, s);
    s = fmaf(a.w, b.w, s);
    return s;
}

// Reduce 32 lane-partial sums across the warp; lane j returns the full sum of
// element j. 31 shuffles total.
__device__ __forceinline__ float bfly32(float (&p)[32], const int lane)
{
#pragma unroll
    for (int m = 16; m >= 1; m >>= 1) {
#pragma unroll
        for (int i = 0; i < m; ++i) {
            const bool up  = (lane & m) != 0;
            float send = up ? p[i] : p[i + m];
            float recv = __shfl_xor_sync(0xffffffffu, send, m);
            float keep = up ? p[i + m] : p[i];
            p[i] = keep + recv;
        }
    }
    return p[0];
}

#define EMIT(val)                                                   \
    do {                                                            \
        p[slot] = (val);                                            \
        ++slot;                                                     \
        if (slot == 32) {                                           \
            float r = bfly32(p, lane);                              \
            ob[tbl[chunk * 32 + lane]] = r;                         \
            ++chunk;                                                \
            slot = 0;                                               \
        }                                                           \
    } while (0)

__global__ __launch_bounds__(128, 3)
void interact_kernel(const float* __restrict__ dense,
                     const float* __restrict__ sparse,
                     float* __restrict__ out)
{
    __shared__ int tbl[352];

    // slot -> triu output index, matching the emission order below.
    for (int s = threadIdx.x; s < NPAIR; s += blockDim.x) {
        int f, g;
        if (s < 171) {                         // phase 1: f<g within low 19
            int f0 = 0;
            while (18 * (f0 + 1) - (f0 + 1) * f0 / 2 <= s) ++f0;
            f = f0;
            g = f + 1 + (s - (18 * f - f * (f - 1) / 2));
        } else if (s < 323) {                  // phase 2: g=19..26 outer, f=0..18 inner
            int t = s - 171;
            g = NLO + t / NLO;
            f = t % NLO;
        } else {                               // phase 3: a<b within high 8
            int t = s - 323;
            int a0 = 0;
            while (7 * (a0 + 1) - (a0 + 1) * a0 / 2 <= t) ++a0;
            int a = a0;
            int b = a + 1 + (t - (7 * a - a * (a - 1) / 2));
            f = NLO + a;
            g = NLO + b;
        }
        tbl[s] = 128 + f * 26 - f * (f - 1) / 2 + (g - f - 1);
    }
    __syncthreads();

    const int gw   = (blockIdx.x * blockDim.x + threadIdx.x) >> 5;  // sample
    const int lane = threadIdx.x & 31;

    const float4* d4 = reinterpret_cast<const float4*>(dense)  + (size_t)gw * 32;
    const float4* s4 = reinterpret_cast<const float4*>(sparse) + (size_t)gw * (FF * 32);
    float* ob = out + (size_t)gw * OUTW;

    // Resident low set: 19 vectors (76 regs).
    float4 v[NLO];
    v[0] = d4[lane];
#pragma unroll
    for (int i = 1; i < NLO; ++i)
        v[i] = s4[(i - 1) * 32 + lane];

    // Depth-2 prefetch of the stream (first DRAM touch overlaps phase 1).
    float4 u0 = s4[18 * 32 + lane];   // vector 19 (row 18)
    float4 u1 = s4[19 * 32 + lane];   // vector 20 (row 19)

    // Dense passthrough.
    ob[lane * 4 + 0] = v[0].x;
    ob[lane * 4 + 1] = v[0].y;
    ob[lane * 4 + 2] = v[0].z;
    ob[lane * 4 + 3] = v[0].w;

    float p[32];
    int slot = 0, chunk = 0;           // constant-folded under full unroll

    // ---- Phase 1: 171 pairs within low 19 ----
#pragma unroll
    for (int f = 0; f < NLO - 1; ++f)
#pragma unroll
        for (int g = f + 1; g < NLO; ++g)
            EMIT(dot4(v[f], v[g]));

    // ---- Phase 2: stream vectors g=19..26, 19 pairs each (152) ----
#pragma unroll
    for (int g = NLO; g < 27; ++g) {
        float4 cur = u0;
        u0 = u1;
        if (g + 2 <= 26)
            u1 = s4[(g + 1) * 32 + lane];   // vector g+2 = row g+1
#pragma unroll
        for (int f = 0; f < NLO; ++f)
            EMIT(dot4(v[f], cur));
    }

    // Keep phase-3 reloads from being hoisted into phase 2 (reg budget).
    asm volatile("" ::: "memory");

    // ---- Phase 3: reload high 8 (L2-hot), 28 within pairs ----
    {
        float4 vh[8];
#pragma unroll
        for (int i = 0; i < 8; ++i)
            vh[i] = s4[(18 + i) * 32 + lane];
#pragma unroll
        for (int a = 0; a < 7; ++a)
#pragma unroll
            for (int b = a + 1; b < 8; ++b)
                EMIT(dot4(vh[a], vh[b]));
    }

    // ---- Tail: 351 = 10*32 + 31; pad slot 31 and flush ----
    p[31] = 0.0f;
    {
        float r = bfly32(p, lane);
        if (lane < 31)
            ob[tbl[10 * 32 + lane]] = r;
    }
}

extern "C" void kernel_launch(void* const* d_in, const int* in_sizes, int n_in,
                              void* d_out, int out_size)
{
    const float* dense  = (const float*)d_in[0];
    const float* sparse = (const float*)d_in[1];
    float* out = (float*)d_out;

    // 16384 samples, 1 warp each, 4 warps/block -> 4096 blocks, 3 blocks/SM.
    interact_kernel<<<4096, 128>>>(dense, sparse, out);
}

// round 5
// speedup vs baseline: 9.3516x; 9.3516x over previous
#include <cuda_runtime.h>

// InteractionArch: out[b] = concat(dense[b] (128),
//        triu(k=1) of Gram([dense[b]; sparse[b].reshape(26,128)]) (351))
// B=16384, D=128, F=26, OUTW=479.
//
// One warp per sample; lane owns dims lane*4..lane*4+3, PACKED as 2 x f32x2
// (64-bit regs) -> all 27 vectors resident in 54 regs (vs 108 scalar fp32).
// Dot per pair: mul.rn.f32x2 + fma.rn.f32x2 + horizontal add (2 FMA-pipe MACs
// instead of 4). Pair partials batched in chunks of 32, reduced with the
// proven 31-shuffle halving butterfly (lane j ends with pair j of the chunk)
// -> sequential coalesced stores in natural triu order, no index table.

#define FF    26
#define NV    27
#define OUTW  479

typedef unsigned long long ull;

__device__ __forceinline__ ull mul2(ull a, ull b)
{
    ull d;
    asm("mul.rn.f32x2 %0, %1, %2;" : "=l"(d) : "l"(a), "l"(b));
    return d;
}
__device__ __forceinline__ ull fma2(ull a, ull b, ull c)
{
    ull d;
    asm("fma.rn.f32x2 %0, %1, %2, %3;" : "=l"(d) : "l"(a), "l"(b), "l"(c));
    return d;
}
__device__ __forceinline__ float hadd2(ull a)
{
    unsigned lo, hi;
    asm("mov.b64 {%0, %1}, %2;" : "=r"(lo), "=r"(hi) : "l"(a));
    return __uint_as_float(lo) + __uint_as_float(hi);
}

// dot over this lane's 4 dims: 2 packed MACs + horizontal add.
__device__ __forceinline__ float dotp(const ulonglong2 a, const ulonglong2 b)
{
    ull t = mul2(a.x, b.x);
    t = fma2(a.y, b.y, t);
    return hadd2(t);
}

// Reduce 32 lane-partial sums across the warp; lane j returns the full sum of
// element j. 31 shuffles total. (Mapping validated by R1 pass.)
__device__ __forceinline__ float bfly32(float (&p)[32], const int lane)
{
#pragma unroll
    for (int m = 16; m >= 1; m >>= 1) {
#pragma unroll
        for (int i = 0; i < m; ++i) {
            const bool up  = (lane & m) != 0;
            float send = up ? p[i] : p[i + m];
            float recv = __shfl_xor_sync(0xffffffffu, send, m);
            float keep = up ? p[i + m] : p[i];
            p[i] = keep + recv;
        }
    }
    return p[0];
}

__global__ __launch_bounds__(128, 4)
void interact_kernel(const float* __restrict__ dense,
                     const float* __restrict__ sparse,
                     float* __restrict__ out)
{
    const int gw   = (blockIdx.x * blockDim.x + threadIdx.x) >> 5;  // sample
    const int lane = threadIdx.x & 31;

    const ulonglong2* d2 = reinterpret_cast<const ulonglong2*>(dense)  + (size_t)gw * 32;
    const ulonglong2* s2 = reinterpret_cast<const ulonglong2*>(sparse) + (size_t)gw * (FF * 32);

    // All 27 vectors resident, packed: 54 registers.
    ulonglong2 v[NV];
    v[0] = d2[lane];
#pragma unroll
    for (int f = 0; f < FF; ++f)
        v[f + 1] = s2[f * 32 + lane];

    float* ob = out + (size_t)gw * OUTW;

    // Dense passthrough (row base only 4B-aligned -> scalar stores).
    {
        unsigned a, b, c, d;
        asm("mov.b64 {%0, %1}, %2;" : "=r"(a), "=r"(b) : "l"(v[0].x));
        asm("mov.b64 {%0, %1}, %2;" : "=r"(c), "=r"(d) : "l"(v[0].y));
        ob[lane * 4 + 0] = __uint_as_float(a);
        ob[lane * 4 + 1] = __uint_as_float(b);
        ob[lane * 4 + 2] = __uint_as_float(c);
        ob[lane * 4 + 3] = __uint_as_float(d);
    }

    float p[32];
    int slot  = 0;        // folded to constants by full unroll
    int obase = 128;

#pragma unroll
    for (int f = 0; f < NV; ++f) {
#pragma unroll
        for (int g = f + 1; g < NV; ++g) {
            p[slot] = dotp(v[f], v[g]);
            ++slot;
            if (slot == 32) {
                float r = bfly32(p, lane);
                ob[obase + lane] = r;
                obase += 32;
                slot = 0;
            }
        }
    }

    // Tail chunk: 351 - 320 = 31 pairs; pad slot 31 with zero.
    p[31] = 0.0f;
    {
        float r = bfly32(p, lane);
        if (lane < 31)
            ob[obase + lane] = r;
    }
}

extern "C" void kernel_launch(void* const* d_in, const int* in_sizes, int n_in,
                              void* d_out, int out_size)
{
    const float* dense  = (const float*)d_in[0];
    const float* sparse = (const float*)d_in[1];
    float* out = (float*)d_out;

    // 16384 samples, 1 warp each, 4 warps/block -> 4096 blocks, 4 blocks/SM.
    interact_kernel<<<4096, 128>>>(dense, sparse, out);
}